// round 14
// baseline (speedup 1.0000x reference)
#include <cuda_runtime.h>
#include <cuda_fp16.h>
#include <cstdint>
#include <cstddef>

// ============================================================================
// Arch feature detection: tcgen05 needs the 'a' target (sm_103a).
// The harness also builds a base compute_103 PTX pass -> guarded fallback.
// ============================================================================
#if defined(__CUDA_ARCH_FEAT_SM103_ALL) || defined(__CUDA_ARCH_FEAT_SM100_ALL) || defined(__CUDA_ARCH_FEAT_SM101_ALL)
#define HAS_TCGEN05 1
#else
#define HAS_TCGEN05 0
#endif

// ============================================================================
// Problem constants
// ============================================================================
#define M_DIM 4096
#define K_DIM 4096
#define N_DIM 11008
#define NW_TOT (N_DIM / 8)
#define GROUP 128

#define TILE_K 32                     // 32 fp16 = 64B = one SW64 row
#define K_CHUNKS (K_DIM / TILE_K)     // 128
#define M_TILES 32                    // 128-row A scratch blocks
#define N_TILES 43                    // 256-col W tiles

#define A_BLK_BYTES (128 * TILE_K * 2)    // 8192
#define W16_BYTES   (256 * TILE_K * 2)    // 16384 (dequantized fp16 stage part)
#define RAW_BYTES   (256 * 4 * 4)         // 4096 (raw int4: 256 n x 4 octs u32)

#define STAGES 3
#define STAGE_BYTES (A_BLK_BYTES + W16_BYTES)   // 24576

// SMEM data layout (offsets from 1024-aligned data_base)
#define SM_SCALE 0                       // 32 g x 256 n x fp16 = 16384
#define SM_ZERO  16384                   // 32 g x 32 words u32 =  4096
#define SM_RAW   20480                   // STAGES x 4096       = 12288
#define SM_STG   32768                   // STAGES x 24576      = 73728
#define SM_DATA_TOTAL 106496
#define GEMM_SMEM_BYTES (2048 + SM_DATA_TOTAL)   // 108544 -> 2 CTAs/SM

// prep kernel block ranges
#define RP_BLOCKS (N_TILES * K_CHUNKS)     // 5504 (qweight repack, nibble-shuffled)
#define AC_BLOCKS (M_TILES * K_CHUNKS)     // 4096 (A convert)

// idesc kind::f16, fp16 a/b, fp32 d (cg1, M=128, N=256)
#define MMA_IDESC_F16 ((1u << 4) | (32u << 17) | (8u << 24))

// Scratch
__device__ __align__(1024) uint16_t g_As[(size_t)M_TILES * K_CHUNKS * (128 * TILE_K)];
// repacked qweight: [n_tile][k_chunk][n(256)][oct(4)] u32, nibble order per oct
// is (k0,k2,k4,k6,k1,k3,k5,k7) so (w>>sh)&0x000F000F extracts (k2i,k2i+1).
__device__ __align__(1024) uint32_t g_Wq[(size_t)N_TILES * K_CHUNKS * 1024];

// ============================================================================
// Base-ISA helpers
// ============================================================================
__device__ __forceinline__ uint32_t smem_u32(const void* p) {
    uint32_t a;
    asm("{ .reg .u64 t; cvta.to.shared.u64 t, %1; cvt.u32.u64 %0, t; }" : "=r"(a) : "l"(p));
    return a;
}

__device__ __forceinline__ uint32_t sw64(uint32_t byte_off) {
    return byte_off ^ ((byte_off >> 3) & 0x30);
}

__device__ __forceinline__ uint32_t pack_h2(float a, float b) {
    uint32_t r;
    asm("{ .reg .f16 lo, hi;\n"
        "cvt.rn.f16.f32 lo, %1;\n"
        "cvt.rn.f16.f32 hi, %2;\n"
        "mov.b32 %0, {lo, hi}; }"
        : "=r"(r) : "f"(a), "f"(b));
    return r;
}

__device__ __forceinline__ uint32_t hsub2_u(uint32_t a, uint32_t b) {
    uint32_t r;
    asm("sub.f16x2 %0, %1, %2;" : "=r"(r) : "r"(a), "r"(b));
    return r;
}

__device__ __forceinline__ uint32_t hmul2_u(uint32_t a, uint32_t b) {
    uint32_t r;
    asm("mul.f16x2 %0, %1, %2;" : "=r"(r) : "r"(a), "r"(b));
    return r;
}

#define MBAR_INIT(addr, cnt) \
    asm volatile("mbarrier.init.shared.b64 [%0], %1;" :: "r"(addr), "r"((uint32_t)(cnt)) : "memory")

#define MBAR_EXPECT_TX(addr, bytes) \
    asm volatile("mbarrier.arrive.expect_tx.shared.b64 _, [%0], %1;" :: "r"(addr), "r"((uint32_t)(bytes)) : "memory")

#define MBAR_ARRIVE(addr) \
    asm volatile("mbarrier.arrive.release.cta.shared.b64 _, [%0];" :: "r"(addr) : "memory")

__device__ __forceinline__ void mbar_wait(uint32_t mbar, uint32_t parity) {
    uint32_t done;
    asm volatile(
        "{ .reg .pred p; mbarrier.try_wait.parity.acquire.cta.shared::cta.b64 p, [%1], %2; selp.b32 %0, 1, 0, p; }"
        : "=r"(done) : "r"(mbar), "r"(parity) : "memory");
    if (!done) {
        asm volatile(
            "{ .reg .pred P1;\n"
            "WL_%=: mbarrier.try_wait.parity.acquire.cta.shared::cta.b64 P1, [%0], %1, 0x989680;\n"
            "@P1 bra.uni WD_%=;\n"
            "bra.uni WL_%=;\n"
            "WD_%=: }"
            :: "r"(mbar), "r"(parity) : "memory");
    }
}

__device__ __forceinline__ void bulk_g2s(uint32_t dst_smem, const void* src_gmem,
                                         uint32_t bytes, uint32_t mbar) {
    asm volatile(
        "cp.async.bulk.shared::cluster.global.mbarrier::complete_tx::bytes [%0], [%1], %2, [%3];"
        :: "r"(dst_smem), "l"(src_gmem), "r"(bytes), "r"(mbar) : "memory");
}

#if HAS_TCGEN05
// ============================================================================
// sm_103a-only helpers
// ============================================================================
__device__ __forceinline__ uint32_t elect_one() {
    uint32_t p;
    asm volatile("{ .reg .pred p; elect.sync _|p, 0xFFFFFFFF; selp.b32 %0, 1, 0, p; }" : "=r"(p));
    return p;
}

// SW64 K-major descriptor: layout=4, version=1 (Blackwell), SBO=32, LBO=1
__device__ __forceinline__ uint64_t make_desc_sw64(uint32_t addr) {
    const uint64_t base = (uint64_t(4) << 61) | (uint64_t(1) << 46) |
                          (uint64_t(32) << 32) | (uint64_t(1) << 16);
    return base | ((uint64_t)(addr >> 4) & 0x3FFF);
}

__device__ __forceinline__ void mma_f16_ss(uint32_t d_tmem, uint64_t a_desc, uint64_t b_desc,
                                           uint32_t idesc, bool acc) {
    uint32_t en = acc ? 1u : 0u;
    asm volatile(
        "{\n\t"
        ".reg .pred p;\n\t"
        "setp.ne.u32 p, %5, 0;\n\t"
        "tcgen05.mma.cta_group::1.kind::f16 [%0], %1, %2, %3, {%4, %4, %4, %4}, p;\n\t"
        "}"
        :: "r"(d_tmem), "l"(a_desc), "l"(b_desc), "r"(idesc), "r"(0u), "r"(en) : "memory");
}

#define TCGEN05_COMMIT(mbar) \
    asm volatile("tcgen05.commit.cta_group::1.mbarrier::arrive::one.shared::cluster.b64 [%0];" \
                 :: "r"(mbar) : "memory")

__device__ __forceinline__ void tcgen05_ld_x32(uint32_t* r, uint32_t tmem_addr) {
    asm volatile(
        "tcgen05.ld.sync.aligned.32x32b.x32.b32 "
        "{%0, %1, %2, %3, %4, %5, %6, %7, "
        " %8, %9, %10, %11, %12, %13, %14, %15, "
        " %16, %17, %18, %19, %20, %21, %22, %23, "
        " %24, %25, %26, %27, %28, %29, %30, %31}, [%32];"
        : "=r"(r[0]), "=r"(r[1]), "=r"(r[2]), "=r"(r[3]),
          "=r"(r[4]), "=r"(r[5]), "=r"(r[6]), "=r"(r[7]),
          "=r"(r[8]), "=r"(r[9]), "=r"(r[10]), "=r"(r[11]),
          "=r"(r[12]), "=r"(r[13]), "=r"(r[14]), "=r"(r[15]),
          "=r"(r[16]), "=r"(r[17]), "=r"(r[18]), "=r"(r[19]),
          "=r"(r[20]), "=r"(r[21]), "=r"(r[22]), "=r"(r[23]),
          "=r"(r[24]), "=r"(r[25]), "=r"(r[26]), "=r"(r[27]),
          "=r"(r[28]), "=r"(r[29]), "=r"(r[30]), "=r"(r[31])
        : "r"(tmem_addr));
}
#endif  // HAS_TCGEN05

// ============================================================================
// Kernel 1 (prep): blocks [0, RP_BLOCKS) repack qweight -> [n][oct] u32 with
// shuffled nibble order (k0,k2,k4,k6,k1,k3,k5,k7); blocks [RP_BLOCKS, ..)
// convert A fp32 -> fp16 SW64-swizzled scratch.
// ============================================================================
__global__ void __launch_bounds__(256) prep_kernel(
    const float* __restrict__ inp,
    const int* __restrict__ qweight
) {
    const int t = threadIdx.x;

    if (blockIdx.x < RP_BLOCKS) {
        const int bid = blockIdx.x;
        const int n_tile = bid >> 7;
        const int k_chunk = bid & 127;
        const int k0 = k_chunk * TILE_K;

        __shared__ uint32_t sq[TILE_K * 33];   // [k][nw], stride 33

        {
            const int k = t >> 3;
            const int nw0 = (t & 7) * 4;
            const uint32_t* src = (const uint32_t*)qweight +
                                  (size_t)(k0 + k) * NW_TOT + n_tile * 32 + nw0;
            #pragma unroll
            for (int i = 0; i < 4; i++) sq[k * 33 + nw0 + i] = src[i];
        }
        __syncthreads();

        const int n = t;                      // 0..255
        const int nw = n >> 3;
        const int nsh = (n & 7) * 4;
        uint32_t w[4];
        #pragma unroll
        for (int oct = 0; oct < 4; oct++) {
            uint32_t word = 0;
            // nibble i <- k = oct*8 + perm(i), perm = 0,2,4,6,1,3,5,7
            #pragma unroll
            for (int i = 0; i < 8; i++) {
                const int kk = oct * 8 + ((i < 4) ? (i * 2) : ((i - 4) * 2 + 1));
                const uint32_t nib = (sq[kk * 33 + nw] >> nsh) & 15u;
                word |= nib << (4 * i);
            }
            w[oct] = word;
        }
        *(uint4*)(g_Wq + (size_t)bid * 1024 + n * 4) = make_uint4(w[0], w[1], w[2], w[3]);
    } else {
        const int bid = blockIdx.x - RP_BLOCKS;
        const int m_tile = bid >> 7;
        const int k_chunk = bid & 127;
        const size_t base_in = (size_t)(m_tile * 128) * K_DIM + k_chunk * TILE_K;
        char* dst_base = (char*)(g_As + (size_t)bid * (128 * TILE_K));

        #pragma unroll
        for (int p = 0; p < 2; p++) {
            const int idx = p * 256 + t;
            const int m_local = idx >> 2;
            const int u = idx & 3;
            const float4* src = (const float4*)(inp + base_in + (size_t)m_local * K_DIM + u * 8);
            const float4 f0 = src[0];
            const float4 f1 = src[1];
            *(uint4*)(dst_base + sw64((uint32_t)(m_local * 64 + u * 16))) =
                make_uint4(pack_h2(f0.x, f0.y), pack_h2(f0.z, f0.w),
                           pack_h2(f1.x, f1.y), pack_h2(f1.z, f1.w));
        }
    }
}

// ============================================================================
// Kernel 2: fused WOQ GEMM, 128M x 256N per CTA, 2 CTAs/SM:
//   warp 0    = mma (AFULL+WFULL waits -> 2 mma -> commit EMPTY)
//   warp 1    = A fetch (8KB bulk, EMPTY-gated)
//   warp 2    = raw-W fetch (4KB bulk, RDONE-gated)
//   warps 4-7 = dequant (raw int4 -> fp16 via f16x2 bit tricks, EMPTY+RFULL
//               gated, arrive RDONE + WFULL)
// Scales fp16 + packed zeros preloaded in SMEM. 3-stage 24KB stages.
// Fused bias + SiLU + mul epilogue on 8 warps. grid = 1376, block = 256.
// ============================================================================
__global__ void __launch_bounds__(256, 2) gemm_kernel(
    const float* __restrict__ bias,
    const float* __restrict__ mul,
    float* __restrict__ out,
    const float* __restrict__ scales,
    const int* __restrict__ qzeros
) {
    extern __shared__ char smem[];
    const uint32_t smem_base = smem_u32(smem);
    const uint32_t data_base = (smem_base + 256 + 1023) & ~1023u;
    const uint32_t doff = data_base - smem_base;

    const int tid = threadIdx.x;
    const int wid = tid >> 5;
    const int lid = tid & 31;
    const int bid = blockIdx.x;
    const int m_tile = bid & (M_TILES - 1);   // m-fast: concurrent CTAs share W via L2
    const int n_tile = bid >> 5;

    const uint32_t AFULL0 = smem_base + 8;    // 3 x 8B (tx)
    const uint32_t WFULL0 = smem_base + 32;   // 3 x 8B, count=4
    const uint32_t RFULL0 = smem_base + 56;   // 3 x 8B (tx)
    const uint32_t RDONE0 = smem_base + 80;   // 3 x 8B, count=4
    const uint32_t EMPTY0 = smem_base + 104;  // 3 x 8B, count=1
    const uint32_t DONE   = smem_base + 128;

#if HAS_TCGEN05
    if (wid == 0) {
        asm volatile("tcgen05.alloc.cta_group::1.sync.aligned.shared::cta.b32 [%0], %1;"
                     :: "r"(smem_base), "r"(256u) : "memory");
        asm volatile("tcgen05.relinquish_alloc_permit.cta_group::1.sync.aligned;");
    }
    if (tid == 0) {
        #pragma unroll
        for (int s = 0; s < STAGES; s++) {
            MBAR_INIT(AFULL0 + s * 8, 1);
            MBAR_INIT(WFULL0 + s * 8, 4);
            MBAR_INIT(RFULL0 + s * 8, 1);
            MBAR_INIT(RDONE0 + s * 8, 4);
            MBAR_INIT(EMPTY0 + s * 8, 1);
        }
        MBAR_INIT(DONE, 1);
        asm volatile("fence.proxy.async.shared::cta;" ::: "memory");
    }

    // ---- preload scales (fp16) + packed zeros for this n_tile ----
    {
        uint16_t* sscale = (uint16_t*)(smem + doff + SM_SCALE);
        uint32_t* szero  = (uint32_t*)(smem + doff + SM_ZERO);
        for (int i = tid; i < 32 * 256; i += 256) {
            const int g = i >> 8, n = i & 255;
            const float s = __ldg(scales + (size_t)g * N_DIM + n_tile * 256 + n);
            sscale[i] = (uint16_t)(pack_h2(s, s) & 0xFFFF);
        }
        for (int i = tid; i < 32 * 32; i += 256) {
            const int g = i >> 5, w = i & 31;
            szero[i] = ((const uint32_t*)qzeros)[(size_t)g * NW_TOT + n_tile * 32 + w];
        }
    }
    __syncthreads();

    uint32_t tmem_base;
    asm volatile("ld.shared.b32 %0, [%1];" : "=r"(tmem_base) : "r"(smem_base));

    if (wid == 1) {
        // ---------------- A fetch warp ----------------
        if (elect_one()) {
            const char* a_src = reinterpret_cast<const char*>(g_As) +
                                (size_t)m_tile * K_CHUNKS * A_BLK_BYTES;
            int rs = 0, es = 0, ep = 0;
            #pragma unroll 1
            for (int j = 0; j < K_CHUNKS; j++) {
                if (j >= STAGES) {
                    mbar_wait(EMPTY0 + es * 8, ep);
                    if (++es == STAGES) { es = 0; ep ^= 1; }
                }
                const uint32_t fb = AFULL0 + rs * 8;
                MBAR_EXPECT_TX(fb, A_BLK_BYTES);
                bulk_g2s(data_base + SM_STG + rs * STAGE_BYTES,
                         a_src + (size_t)j * A_BLK_BYTES, A_BLK_BYTES, fb);
                if (++rs == STAGES) rs = 0;
            }
        }
        __syncwarp();
    } else if (wid == 2) {
        // ---------------- raw-W fetch warp ----------------
        if (elect_one()) {
            const char* wq_src = reinterpret_cast<const char*>(g_Wq) +
                                 (size_t)n_tile * K_CHUNKS * RAW_BYTES;
            int rs = 0, es = 0, ep = 0;
            #pragma unroll 1
            for (int j = 0; j < K_CHUNKS; j++) {
                if (j >= STAGES) {
                    mbar_wait(RDONE0 + es * 8, ep);
                    if (++es == STAGES) { es = 0; ep ^= 1; }
                }
                const uint32_t fb = RFULL0 + rs * 8;
                MBAR_EXPECT_TX(fb, RAW_BYTES);
                bulk_g2s(data_base + SM_RAW + rs * RAW_BYTES,
                         wq_src + (size_t)j * RAW_BYTES, RAW_BYTES, fb);
                if (++rs == STAGES) rs = 0;
            }
        }
        __syncwarp();
    } else if (wid == 0) {
        // ---------------- mma warp ----------------
        if (elect_one()) {
            int fs = 0, fp = 0;
            #pragma unroll 1
            for (int it = 0; it < K_CHUNKS; it++) {
                mbar_wait(AFULL0 + fs * 8, fp);
                mbar_wait(WFULL0 + fs * 8, fp);
                const uint32_t st = data_base + SM_STG + fs * STAGE_BYTES;
                const uint64_t ad = make_desc_sw64(st);
                const uint64_t bd = make_desc_sw64(st + A_BLK_BYTES);
                #pragma unroll
                for (int ks = 0; ks < 2; ks++)
                    mma_f16_ss(tmem_base, ad + ks * 2, bd + ks * 2,
                               MMA_IDESC_F16, (it | ks) != 0);
                TCGEN05_COMMIT(EMPTY0 + fs * 8);
                if (++fs == STAGES) { fs = 0; fp ^= 1; }
            }
            TCGEN05_COMMIT(DONE);
        }
        __syncwarp();
    } else if (wid >= 4) {
        // ---------------- dequant warps (4..7) ----------------
        const int t2 = (wid - 4) * 32 + lid;          // 0..127
        const uint16_t* sscale = (const uint16_t*)(smem + doff + SM_SCALE);
        const uint32_t* szero  = (const uint32_t*)(smem + doff + SM_ZERO);

        int fs = 0, fp = 0, es = 0, ep = 0;
        #pragma unroll 1
        for (int j = 0; j < K_CHUNKS; j++) {
            if (j >= STAGES) {
                mbar_wait(EMPTY0 + es * 8, ep);
                if (++es == STAGES) { es = 0; ep ^= 1; }
            }
            mbar_wait(RFULL0 + fs * 8, fp);

            const int g = j >> 2;
            const uint32_t* raw = (const uint32_t*)(smem + doff + SM_RAW + fs * RAW_BYTES);
            char* wdst = smem + doff + SM_STG + fs * STAGE_BYTES + A_BLK_BYTES;

            #pragma unroll
            for (int rep = 0; rep < 2; rep++) {
                const int n = t2 * 2 + rep;
                const uint16_t sh = sscale[g * 256 + n];
                const uint32_t s2 = (uint32_t)sh | ((uint32_t)sh << 16);
                const uint32_t z = (szero[g * 32 + (n >> 3)] >> ((n & 7) * 4)) & 15u;
                const uint32_t hz2 = 0x64006400u + z * 0x00010001u;
                const uint4 rw = *(const uint4*)(raw + n * 4);
                const uint32_t rr[4] = {rw.x, rw.y, rw.z, rw.w};
                #pragma unroll
                for (int oct = 0; oct < 4; oct++) {
                    const uint32_t r = rr[oct];
                    uint32_t h[4];
                    #pragma unroll
                    for (int q = 0; q < 4; q++) {
                        const uint32_t x = ((r >> (4 * q)) & 0x000F000Fu) | 0x64006400u;
                        h[q] = hmul2_u(hsub2_u(x, hz2), s2);
                    }
                    *(uint4*)(wdst + sw64((uint32_t)(n * 64 + oct * 16))) =
                        make_uint4(h[0], h[1], h[2], h[3]);
                }
            }
            asm volatile("fence.proxy.async.shared::cta;" ::: "memory");
            __syncwarp();
            if (lid == 0) {
                MBAR_ARRIVE(RDONE0 + fs * 8);
                MBAR_ARRIVE(WFULL0 + fs * 8);
            }
            if (++fs == STAGES) { fs = 0; fp ^= 1; }
        }
        __syncwarp();
    }

    // ------ epilogue: warps 0-3 cols 0..127, warps 4-7 cols 128..255 ---------
    mbar_wait(DONE, 0);
    asm volatile("tcgen05.fence::after_thread_sync;" ::: "memory");

    const int half = wid >> 2;
    const int m = m_tile * 128 + (wid & 3) * 32 + lid;
    const int n_base = n_tile * 256 + half * 128;
    const float4* mul4 = reinterpret_cast<const float4*>(mul + (size_t)m * N_DIM + n_base);
    float4* out4 = reinterpret_cast<float4*>(out + (size_t)m * N_DIM + n_base);

    #pragma unroll 1
    for (int cc = 0; cc < 4; cc++) {
        uint32_t d[32];
        tcgen05_ld_x32(d, tmem_base + half * 128 + cc * 32);
        asm volatile("tcgen05.wait::ld.sync.aligned;" ::: "memory");
        #pragma unroll
        for (int v = 0; v < 8; v++) {
            const float4 mv = mul4[cc * 8 + v];
            const float mvf[4] = {mv.x, mv.y, mv.z, mv.w};
            float o[4];
            #pragma unroll
            for (int e = 0; e < 4; e++) {
                const int jj = v * 4 + e;
                const float x = __uint_as_float(d[jj]) + __ldg(bias + n_base + cc * 32 + jj);
                const float sg = 1.0f / (1.0f + __expf(-x));
                o[e] = x * sg * mvf[e];
            }
            out4[cc * 8 + v] = make_float4(o[0], o[1], o[2], o[3]);
        }
    }

    __syncthreads();
    if (wid == 0) {
        asm volatile("tcgen05.dealloc.cta_group::1.sync.aligned.b32 %0, %1;"
                     :: "r"(tmem_base), "r"(256u));
    }

#else
    // ------------------------------------------------------------- fallback
    // Base compute_103 pass: compiles only; tcgen05 cubin is selected on the
    // sm_103a GPU. Correct scalar reference (slow) preserving semantics.
    (void)doff;
    for (int idx = tid; idx < 128 * 256; idx += 256) {
        const int ml = idx >> 8;
        const int nl = idx & 255;
        const int mg = m_tile * 128 + ml;
        const int ng = n_tile * 256 + nl;
        float acc = 0.0f;
        for (int kc = 0; kc < K_CHUNKS; kc++) {
            const int g = kc >> 2;
            const float s = __half2float(__float2half(
                __ldg(scales + (size_t)g * N_DIM + ng)));
            const float z = (float)((((const uint32_t*)qzeros)[(size_t)g * NW_TOT + n_tile * 32 + (nl >> 3)] >> ((nl & 7) * 4)) & 15u);
            const uint32_t* raw = g_Wq + (size_t)(n_tile * K_CHUNKS + kc) * 1024 + nl * 4;
            const uint16_t* arow = g_As + (size_t)(m_tile * K_CHUNKS + kc) * (128 * TILE_K);
            for (int k = 0; k < TILE_K; k++) {
                const int oct = k >> 3, kr = k & 7;
                const int i = (kr & 1) ? (4 + (kr >> 1)) : (kr >> 1);
                const float q = (float)((raw[oct] >> (4 * i)) & 15u);
                const float w = __half2float(__float2half((q - z) * s));
                const uint32_t aoff = sw64((uint32_t)(ml * 64 + (k >> 3) * 16)) + (k & 7) * 2;
                const __half ah = *(const __half*)((const char*)arow + aoff);
                acc += __half2float(ah) * w;
            }
        }
        const float x = acc + __ldg(bias + ng);
        const float sg = 1.0f / (1.0f + __expf(-x));
        out[(size_t)mg * N_DIM + ng] = x * sg * mul[(size_t)mg * N_DIM + ng];
    }
#endif
}

// ============================================================================
// Launch
// ============================================================================
extern "C" void kernel_launch(void* const* d_in, const int* in_sizes, int n_in,
                              void* d_out, int out_size) {
    const float* inp     = (const float*)d_in[0];
    const int*   qweight = (const int*)d_in[1];
    const float* scales  = (const float*)d_in[2];
    const int*   qzeros  = (const int*)d_in[3];
    const float* bias    = (const float*)d_in[4];
    const float* mul     = (const float*)d_in[5];
    float* out = (float*)d_out;

    cudaFuncSetAttribute(gemm_kernel, cudaFuncAttributeMaxDynamicSharedMemorySize,
                         GEMM_SMEM_BYTES);

    prep_kernel<<<RP_BLOCKS + AC_BLOCKS, 256>>>(inp, qweight);
    gemm_kernel<<<M_TILES * N_TILES, 256, GEMM_SMEM_BYTES>>>(bias, mul, out, scales, qzeros);
}

// round 16
// speedup vs baseline: 1.5003x; 1.5003x over previous
#include <cuda_runtime.h>
#include <cuda_fp16.h>
#include <cstdint>
#include <cstddef>

// ============================================================================
// Arch feature detection: tcgen05 needs the 'a' target (sm_103a).
// The harness also builds a base compute_103 PTX pass -> guarded fallback.
// ============================================================================
#if defined(__CUDA_ARCH_FEAT_SM103_ALL) || defined(__CUDA_ARCH_FEAT_SM100_ALL) || defined(__CUDA_ARCH_FEAT_SM101_ALL)
#define HAS_TCGEN05 1
#else
#define HAS_TCGEN05 0
#endif

// ============================================================================
// Problem constants
// ============================================================================
#define M_DIM 4096
#define K_DIM 4096
#define N_DIM 11008
#define NW_TOT (N_DIM / 8)
#define GROUP 128

#define TILE_K 32                     // 32 fp16 = 64B = one SW64 row
#define K_CHUNKS (K_DIM / TILE_K)     // 128
#define M_TILES 32                    // 128-row A scratch blocks
#define N_TILES 43                    // 256-row W scratch blocks

#define A_BLK_BYTES (128 * TILE_K * 2)    // 8192
#define B_BLK_BYTES (256 * TILE_K * 2)    // 16384

// GEMM pipeline: stage = A(8K) + B(16K) = 24KB, 4 stages -> 96KB => 2 CTAs/SM
#define STAGES 4
#define STAGE_BYTES (A_BLK_BYTES + B_BLK_BYTES)       // 24576
#define GEMM_SMEM_BYTES (2048 + STAGES * STAGE_BYTES) // 100352

// fused prep kernel block ranges
#define DQ_BLOCKS (N_TILES * K_CHUNKS)     // 5504
#define AC_BLOCKS (M_TILES * K_CHUNKS)     // 4096

// idesc kind::f16, fp16 a/b, fp32 d (cg1, M=128, N=256)
#define MMA_IDESC_F16 ((1u << 4) | (32u << 17) | (8u << 24))

// Scratch: pre-tiled, pre-SW64-swizzled fp16 operands (64B rows, K=32 per block).
__device__ __align__(1024) uint16_t g_As[(size_t)M_TILES * K_CHUNKS * (128 * TILE_K)];
__device__ __align__(1024) uint16_t g_Ws[(size_t)N_TILES * K_CHUNKS * (256 * TILE_K)];

// ============================================================================
// Base-ISA helpers
// ============================================================================
__device__ __forceinline__ uint32_t smem_u32(const void* p) {
    uint32_t a;
    asm("{ .reg .u64 t; cvta.to.shared.u64 t, %1; cvt.u32.u64 %0, t; }" : "=r"(a) : "l"(p));
    return a;
}

__device__ __forceinline__ uint32_t sw64(uint32_t byte_off) {
    return byte_off ^ ((byte_off >> 3) & 0x30);
}

__device__ __forceinline__ uint32_t pack_h2(float a, float b) {
    uint32_t r;
    asm("{ .reg .f16 lo, hi;\n"
        "cvt.rn.f16.f32 lo, %1;\n"
        "cvt.rn.f16.f32 hi, %2;\n"
        "mov.b32 %0, {lo, hi}; }"
        : "=r"(r) : "f"(a), "f"(b));
    return r;
}

#define MBAR_INIT(addr, cnt) \
    asm volatile("mbarrier.init.shared.b64 [%0], %1;" :: "r"(addr), "r"((uint32_t)(cnt)) : "memory")

#define MBAR_EXPECT_TX(addr, bytes) \
    asm volatile("mbarrier.arrive.expect_tx.shared.b64 _, [%0], %1;" :: "r"(addr), "r"((uint32_t)(bytes)) : "memory")

#define MBAR_ARRIVE(addr) \
    asm volatile("mbarrier.arrive.release.cta.shared.b64 _, [%0];" :: "r"(addr) : "memory")

__device__ __forceinline__ void mbar_wait(uint32_t mbar, uint32_t parity) {
    uint32_t done;
    asm volatile(
        "{ .reg .pred p; mbarrier.try_wait.parity.acquire.cta.shared::cta.b64 p, [%1], %2; selp.b32 %0, 1, 0, p; }"
        : "=r"(done) : "r"(mbar), "r"(parity) : "memory");
    if (!done) {
        asm volatile(
            "{ .reg .pred P1;\n"
            "WL_%=: mbarrier.try_wait.parity.acquire.cta.shared::cta.b64 P1, [%0], %1, 0x989680;\n"
            "@P1 bra.uni WD_%=;\n"
            "bra.uni WL_%=;\n"
            "WD_%=: }"
            :: "r"(mbar), "r"(parity) : "memory");
    }
}

__device__ __forceinline__ void bulk_g2s(uint32_t dst_smem, const void* src_gmem,
                                         uint32_t bytes, uint32_t mbar) {
    asm volatile(
        "cp.async.bulk.shared::cluster.global.mbarrier::complete_tx::bytes [%0], [%1], %2, [%3];"
        :: "r"(dst_smem), "l"(src_gmem), "r"(bytes), "r"(mbar) : "memory");
}

// legacy f16 mma (sm_80 base ISA) -- fallback path only
__device__ __forceinline__ void mma_sync_f16(float* d, const uint32_t* a, const uint32_t* b) {
    asm volatile(
        "mma.sync.aligned.m16n8k16.row.col.f32.f16.f16.f32 "
        "{%0, %1, %2, %3}, {%4, %5, %6, %7}, {%8, %9}, {%0, %1, %2, %3};"
        : "+f"(d[0]), "+f"(d[1]), "+f"(d[2]), "+f"(d[3])
        : "r"(a[0]), "r"(a[1]), "r"(a[2]), "r"(a[3]), "r"(b[0]), "r"(b[1]));
}

#if HAS_TCGEN05
// ============================================================================
// sm_103a-only helpers
// ============================================================================
__device__ __forceinline__ uint32_t elect_one() {
    uint32_t p;
    asm volatile("{ .reg .pred p; elect.sync _|p, 0xFFFFFFFF; selp.b32 %0, 1, 0, p; }" : "=r"(p));
    return p;
}

// SW64 K-major descriptor: layout=4, version=1 (Blackwell), SBO=32, LBO=1
__device__ __forceinline__ uint64_t make_desc_sw64(uint32_t addr) {
    const uint64_t base = (uint64_t(4) << 61) | (uint64_t(1) << 46) |
                          (uint64_t(32) << 32) | (uint64_t(1) << 16);
    return base | ((uint64_t)(addr >> 4) & 0x3FFF);
}

__device__ __forceinline__ void mma_f16_ss(uint32_t d_tmem, uint64_t a_desc, uint64_t b_desc,
                                           uint32_t idesc, bool acc) {
    uint32_t en = acc ? 1u : 0u;
    asm volatile(
        "{\n\t"
        ".reg .pred p;\n\t"
        "setp.ne.u32 p, %5, 0;\n\t"
        "tcgen05.mma.cta_group::1.kind::f16 [%0], %1, %2, %3, {%4, %4, %4, %4}, p;\n\t"
        "}"
        :: "r"(d_tmem), "l"(a_desc), "l"(b_desc), "r"(idesc), "r"(0u), "r"(en) : "memory");
}

#define TCGEN05_COMMIT(mbar) \
    asm volatile("tcgen05.commit.cta_group::1.mbarrier::arrive::one.shared::cluster.b64 [%0];" \
                 :: "r"(mbar) : "memory")

__device__ __forceinline__ void tcgen05_ld_x32(uint32_t* r, uint32_t tmem_addr) {
    asm volatile(
        "tcgen05.ld.sync.aligned.32x32b.x32.b32 "
        "{%0, %1, %2, %3, %4, %5, %6, %7, "
        " %8, %9, %10, %11, %12, %13, %14, %15, "
        " %16, %17, %18, %19, %20, %21, %22, %23, "
        " %24, %25, %26, %27, %28, %29, %30, %31}, [%32];"
        : "=r"(r[0]), "=r"(r[1]), "=r"(r[2]), "=r"(r[3]),
          "=r"(r[4]), "=r"(r[5]), "=r"(r[6]), "=r"(r[7]),
          "=r"(r[8]), "=r"(r[9]), "=r"(r[10]), "=r"(r[11]),
          "=r"(r[12]), "=r"(r[13]), "=r"(r[14]), "=r"(r[15]),
          "=r"(r[16]), "=r"(r[17]), "=r"(r[18]), "=r"(r[19]),
          "=r"(r[20]), "=r"(r[21]), "=r"(r[22]), "=r"(r[23]),
          "=r"(r[24]), "=r"(r[25]), "=r"(r[26]), "=r"(r[27]),
          "=r"(r[28]), "=r"(r[29]), "=r"(r[30]), "=r"(r[31])
        : "r"(tmem_addr));
}
#endif  // HAS_TCGEN05

// ============================================================================
// Kernel 1 (fused prep): blocks [0, DQ_BLOCKS) dequantize int4 -> fp16 W
// scratch; blocks [DQ_BLOCKS, ..) convert A fp32 -> fp16. SMEM-free swizzled
// STG paths (SW64 permutes 16B units; aligned uint4 stores land correctly).
// ============================================================================
__global__ void __launch_bounds__(256) prep_kernel(
    const float* __restrict__ inp,
    const int* __restrict__ qweight,
    const float* __restrict__ scales,
    const int* __restrict__ qzeros
) {
    const int t = threadIdx.x;

    if (blockIdx.x < DQ_BLOCKS) {
        // -------- dequant: int4 -> fp16, [N,K=32] tiled + SW64 swizzled -------
        const int bid = blockIdx.x;
        const int n_tile = bid >> 7;
        const int k_chunk = bid & 127;
        const int k0 = k_chunk * TILE_K;
        const int g = k0 >> 7;

        __shared__ uint32_t sq[TILE_K * 33];
        __shared__ uint32_t sz[32];

        {
            const int k = t >> 3;
            const int nw0 = (t & 7) * 4;
            const uint32_t* src = (const uint32_t*)qweight +
                                  (size_t)(k0 + k) * NW_TOT + n_tile * 32 + nw0;
            #pragma unroll
            for (int i = 0; i < 4; i++) sq[k * 33 + nw0 + i] = src[i];
            if (t < 32) sz[t] = ((const uint32_t*)qzeros)[(size_t)g * NW_TOT + n_tile * 32 + t];
        }
        __syncthreads();

        char* dst_base = (char*)(g_Ws + (size_t)bid * (256 * TILE_K));
        #pragma unroll
        for (int p = 0; p < 4; p++) {
            const int idx = p * 256 + t;
            const int n_local = idx >> 2;
            const int u = idx & 3;
            const int nw = n_local >> 3;
            const int nib = (n_local & 7) * 4;
            const float z = (float)((sz[nw] >> nib) & 15u);
            const float s = __ldg(scales + (size_t)g * N_DIM + n_tile * 256 + n_local);
            float w[8];
            #pragma unroll
            for (int e = 0; e < 8; e++) {
                const float q = (float)((sq[(u * 8 + e) * 33 + nw] >> nib) & 15u);
                w[e] = (q - z) * s;
            }
            *(uint4*)(dst_base + sw64((uint32_t)(n_local * 64 + u * 16))) =
                make_uint4(pack_h2(w[0], w[1]), pack_h2(w[2], w[3]),
                           pack_h2(w[4], w[5]), pack_h2(w[6], w[7]));
        }
    } else {
        // -------- aconv: fp32 -> fp16(rn), [M,K=32] tiled + SW64 swizzled -----
        const int bid = blockIdx.x - DQ_BLOCKS;
        const int m_tile = bid >> 7;
        const int k_chunk = bid & 127;
        const size_t base_in = (size_t)(m_tile * 128) * K_DIM + k_chunk * TILE_K;
        char* dst_base = (char*)(g_As + (size_t)bid * (128 * TILE_K));

        #pragma unroll
        for (int p = 0; p < 2; p++) {
            const int idx = p * 256 + t;
            const int m_local = idx >> 2;
            const int u = idx & 3;
            const float4* src = (const float4*)(inp + base_in + (size_t)m_local * K_DIM + u * 8);
            const float4 f0 = src[0];
            const float4 f1 = src[1];
            *(uint4*)(dst_base + sw64((uint32_t)(m_local * 64 + u * 16))) =
                make_uint4(pack_h2(f0.x, f0.y), pack_h2(f0.z, f0.w),
                           pack_h2(f1.x, f1.y), pack_h2(f1.z, f1.w));
        }
    }
}

// ============================================================================
// Kernel 2: 128M x 256N fp16 GEMM, 2 CTAs per SM (96KB smem, 256 TMEM cols).
//   warp 0 = mma driver (FULL-wait -> 2 mma -> commit EMPTY)
//   warp 1 = fetch warp (EMPTY-gated 2 bulk copies/chunk)
// Single TMEM accumulator (256 cols), 4-stage (24KB) pipeline.
// Fused bias + SiLU + mul epilogue on 8 warps. grid = 1376, block = 256.
// ============================================================================
__global__ void __launch_bounds__(256, 2) gemm_kernel(
    const float* __restrict__ bias,
    const float* __restrict__ mul,
    float* __restrict__ out
) {
    extern __shared__ char smem[];
    const uint32_t smem_base = smem_u32(smem);
    const uint32_t data_base = (smem_base + 128 + 1023) & ~1023u;

    const int tid = threadIdx.x;
    const int wid = tid >> 5;
    const int lid = tid & 31;
    const int bid = blockIdx.x;
    const int m_tile = bid & (M_TILES - 1);   // m-fast: concurrent CTAs share B via L2
    const int n_tile = bid >> 5;

    const uint32_t FULL0  = smem_base + 8;    // 4 x 8B
    const uint32_t EMPTY0 = smem_base + 40;   // 4 x 8B
    const uint32_t DONE   = smem_base + 72;

#if HAS_TCGEN05
    if (wid == 0) {
        asm volatile("tcgen05.alloc.cta_group::1.sync.aligned.shared::cta.b32 [%0], %1;"
                     :: "r"(smem_base), "r"(256u) : "memory");
        asm volatile("tcgen05.relinquish_alloc_permit.cta_group::1.sync.aligned;");
    }
    if (tid == 0) {
        #pragma unroll
        for (int s = 0; s < STAGES; s++) {
            MBAR_INIT(FULL0 + s * 8, 1);
            MBAR_INIT(EMPTY0 + s * 8, 1);
        }
        MBAR_INIT(DONE, 1);
        asm volatile("fence.proxy.async.shared::cta;" ::: "memory");
    }
    __syncthreads();

    uint32_t tmem_base;
    asm volatile("ld.shared.b32 %0, [%1];" : "=r"(tmem_base) : "r"(smem_base));

    if (wid == 1) {
        // ---------------- fetch warp: EMPTY-gated bulk refills ----------------
        if (elect_one()) {
            const char* a_src = reinterpret_cast<const char*>(g_As) +
                                (size_t)m_tile * K_CHUNKS * A_BLK_BYTES;
            const char* b_src = reinterpret_cast<const char*>(g_Ws) +
                                (size_t)n_tile * K_CHUNKS * B_BLK_BYTES;

            int rs = 0;
            int es = 0, ep = 0;
            #pragma unroll 1
            for (int j = 0; j < K_CHUNKS; j++) {
                if (j >= STAGES) {
                    mbar_wait(EMPTY0 + es * 8, ep);
                    if (++es == STAGES) { es = 0; ep ^= 1; }
                }
                const uint32_t fb = FULL0 + rs * 8;
                const uint32_t st = data_base + rs * STAGE_BYTES;
                MBAR_EXPECT_TX(fb, STAGE_BYTES);
                bulk_g2s(st,               a_src + (size_t)j * A_BLK_BYTES, A_BLK_BYTES, fb);
                bulk_g2s(st + A_BLK_BYTES, b_src + (size_t)j * B_BLK_BYTES, B_BLK_BYTES, fb);
                if (++rs == STAGES) rs = 0;
            }
        }
        __syncwarp();
    } else if (wid == 0) {
        // ---------------- mma warp: pure tensor issue ------------------------
        if (elect_one()) {
            int fs = 0, fp = 0;
            #pragma unroll 1
            for (int it = 0; it < K_CHUNKS; it++) {
                mbar_wait(FULL0 + fs * 8, fp);
                const uint32_t st = data_base + fs * STAGE_BYTES;
                const uint64_t ad = make_desc_sw64(st);
                const uint64_t bd = make_desc_sw64(st + A_BLK_BYTES);
                #pragma unroll
                for (int ks = 0; ks < 2; ks++)    // 2 x K=16 fp16 steps = 32 K
                    mma_f16_ss(tmem_base, ad + ks * 2, bd + ks * 2,
                               MMA_IDESC_F16, (it | ks) != 0);
                TCGEN05_COMMIT(EMPTY0 + fs * 8);
                if (++fs == STAGES) { fs = 0; fp ^= 1; }
            }
            TCGEN05_COMMIT(DONE);
        }
        __syncwarp();
    }

    // ------ epilogue: warps 0-3 cols 0..127, warps 4-7 cols 128..255 ---------
    mbar_wait(DONE, 0);
    asm volatile("tcgen05.fence::after_thread_sync;" ::: "memory");

    const int half = wid >> 2;
    const int m = m_tile * 128 + (wid & 3) * 32 + lid;
    const int n_base = n_tile * 256 + half * 128;
    const float4* mul4 = reinterpret_cast<const float4*>(mul + (size_t)m * N_DIM + n_base);
    float4* out4 = reinterpret_cast<float4*>(out + (size_t)m * N_DIM + n_base);

    #pragma unroll 1
    for (int cc = 0; cc < 4; cc++) {
        uint32_t d[32];
        tcgen05_ld_x32(d, tmem_base + half * 128 + cc * 32);
        asm volatile("tcgen05.wait::ld.sync.aligned;" ::: "memory");
        #pragma unroll
        for (int v = 0; v < 8; v++) {
            const float4 mv = mul4[cc * 8 + v];
            const float mvf[4] = {mv.x, mv.y, mv.z, mv.w};
            float o[4];
            #pragma unroll
            for (int e = 0; e < 4; e++) {
                const int j = v * 4 + e;
                const float x = __uint_as_float(d[j]) + __ldg(bias + n_base + cc * 32 + j);
                const float sg = 1.0f / (1.0f + __expf(-x));
                o[e] = x * sg * mvf[e];
            }
            out4[cc * 8 + v] = make_float4(o[0], o[1], o[2], o[3]);
        }
    }

    __syncthreads();
    if (wid == 0) {
        asm volatile("tcgen05.dealloc.cta_group::1.sync.aligned.b32 %0, %1;"
                     :: "r"(tmem_base), "r"(256u));
    }

#else
    // ------------------------------------------------------------- fallback path
    // Base compute_103 pass (never selected on sm_103a hardware; must compile).
    // 8 warps: 2(M) x 4(N) warp grid of 64x64; m16n8k16 f16 mma; SW64 rows.
    if (tid == 0) {
        #pragma unroll
        for (int s = 0; s < STAGES; s++) {
            MBAR_INIT(FULL0 + s * 8, 1);
            MBAR_INIT(EMPTY0 + s * 8, 8);
        }
        asm volatile("fence.proxy.async.shared::cta;" ::: "memory");
    }
    __syncthreads();

    const uint32_t data_off = data_base - smem_base;
    const int m0w = (wid >> 2) * 64;
    const int n0w = (wid & 3) * 64;
    const int ar = lid >> 2;
    const int ac = lid & 3;

    const char* a_src = reinterpret_cast<const char*>(g_As) +
                        (size_t)m_tile * K_CHUNKS * A_BLK_BYTES;
    const char* b_src = reinterpret_cast<const char*>(g_Ws) +
                        (size_t)n_tile * K_CHUNKS * B_BLK_BYTES;

    if (tid == 0) {
        #pragma unroll
        for (int j = 0; j < STAGES - 1; j++) {
            const uint32_t fb = FULL0 + j * 8;
            MBAR_EXPECT_TX(fb, STAGE_BYTES);
            bulk_g2s(data_base + j * STAGE_BYTES,
                     a_src + (size_t)j * A_BLK_BYTES, A_BLK_BYTES, fb);
            bulk_g2s(data_base + j * STAGE_BYTES + A_BLK_BYTES,
                     b_src + (size_t)j * B_BLK_BYTES, B_BLK_BYTES, fb);
        }
    }

    float acc[4][8][4];
    #pragma unroll
    for (int mi = 0; mi < 4; mi++)
        #pragma unroll
        for (int ni = 0; ni < 8; ni++)
            #pragma unroll
            for (int e = 0; e < 4; e++) acc[mi][ni][e] = 0.0f;

    #pragma unroll 1
    for (int it = 0; it < K_CHUNKS; it++) {
        const int s = it & 3;
        mbar_wait(FULL0 + s * 8, (it >> 2) & 1);

        const uint32_t a_base = data_off + s * STAGE_BYTES;
        const uint32_t b_base = a_base + A_BLK_BYTES;

        #pragma unroll
        for (int ks = 0; ks < 2; ks++) {
            uint32_t afr[2][4];
            #pragma unroll
            for (int mi = 0; mi < 2; mi++) {
                const int r0 = m0w + mi * 16 + ar;
                const int c = ks * 16 + ac * 2;
                afr[mi][0] = *(const uint32_t*)(smem + a_base + sw64(r0 * 64 + c * 2));
                afr[mi][1] = *(const uint32_t*)(smem + a_base + sw64((r0 + 8) * 64 + c * 2));
                afr[mi][2] = *(const uint32_t*)(smem + a_base + sw64(r0 * 64 + (c + 8) * 2));
                afr[mi][3] = *(const uint32_t*)(smem + a_base + sw64((r0 + 8) * 64 + (c + 8) * 2));
            }
            uint32_t afr2[2][4];
            #pragma unroll
            for (int mi = 0; mi < 2; mi++) {
                const int r0 = m0w + (mi + 2) * 16 + ar;
                const int c = ks * 16 + ac * 2;
                afr2[mi][0] = *(const uint32_t*)(smem + a_base + sw64(r0 * 64 + c * 2));
                afr2[mi][1] = *(const uint32_t*)(smem + a_base + sw64((r0 + 8) * 64 + c * 2));
                afr2[mi][2] = *(const uint32_t*)(smem + a_base + sw64(r0 * 64 + (c + 8) * 2));
                afr2[mi][3] = *(const uint32_t*)(smem + a_base + sw64((r0 + 8) * 64 + (c + 8) * 2));
            }
            uint32_t bfr[8][2];
            #pragma unroll
            for (int ni = 0; ni < 8; ni++) {
                const int bn = n0w + ni * 8 + ar;
                const int bk = ks * 16 + ac * 2;
                bfr[ni][0] = *(const uint32_t*)(smem + b_base + sw64(bn * 64 + bk * 2));
                bfr[ni][1] = *(const uint32_t*)(smem + b_base + sw64(bn * 64 + (bk + 8) * 2));
            }
            #pragma unroll
            for (int mi = 0; mi < 2; mi++)
                #pragma unroll
                for (int ni = 0; ni < 8; ni++) {
                    mma_sync_f16(acc[mi][ni], afr[mi], bfr[ni]);
                    mma_sync_f16(acc[mi + 2][ni], afr2[mi], bfr[ni]);
                }
        }

        if (lid == 0) MBAR_ARRIVE(EMPTY0 + s * 8);

        const int j = it + STAGES - 1;
        if (j < K_CHUNKS && tid == 0) {
            const int s2 = j & 3;
            if (j >= STAGES) mbar_wait(EMPTY0 + s2 * 8, ((j - STAGES) >> 2) & 1);
            const uint32_t fb = FULL0 + s2 * 8;
            MBAR_EXPECT_TX(fb, STAGE_BYTES);
            bulk_g2s(data_base + s2 * STAGE_BYTES,
                     a_src + (size_t)j * A_BLK_BYTES, A_BLK_BYTES, fb);
            bulk_g2s(data_base + s2 * STAGE_BYTES + A_BLK_BYTES,
                     b_src + (size_t)j * B_BLK_BYTES, B_BLK_BYTES, fb);
        }
    }

    const int gm0 = m_tile * 128 + m0w;
    const int gn0 = n_tile * 256 + n0w;
    #pragma unroll
    for (int mi = 0; mi < 4; mi++) {
        #pragma unroll
        for (int hrow = 0; hrow < 2; hrow++) {
            const int m = gm0 + mi * 16 + hrow * 8 + (lid >> 2);
            #pragma unroll
            for (int ni = 0; ni < 8; ni++) {
                const int n = gn0 + ni * 8 + (lid & 3) * 2;
                const float2 mv = *reinterpret_cast<const float2*>(mul + (size_t)m * N_DIM + n);
                float o[2];
                #pragma unroll
                for (int e = 0; e < 2; e++) {
                    const float x = acc[mi][ni][hrow * 2 + e] + __ldg(bias + n + e);
                    const float sg = 1.0f / (1.0f + __expf(-x));
                    o[e] = x * sg * ((e == 0) ? mv.x : mv.y);
                }
                *reinterpret_cast<float2*>(out + (size_t)m * N_DIM + n) = make_float2(o[0], o[1]);
            }
        }
    }
#endif
}

// ============================================================================
// Launch
// ============================================================================
extern "C" void kernel_launch(void* const* d_in, const int* in_sizes, int n_in,
                              void* d_out, int out_size) {
    const float* inp     = (const float*)d_in[0];
    const int*   qweight = (const int*)d_in[1];
    const float* scales  = (const float*)d_in[2];
    const int*   qzeros  = (const int*)d_in[3];
    const float* bias    = (const float*)d_in[4];
    const float* mul     = (const float*)d_in[5];
    float* out = (float*)d_out;

    cudaFuncSetAttribute(gemm_kernel, cudaFuncAttributeMaxDynamicSharedMemorySize,
                         GEMM_SMEM_BYTES);

    prep_kernel<<<DQ_BLOCKS + AC_BLOCKS, 256>>>(inp, qweight, scales, qzeros);
    gemm_kernel<<<M_TILES * N_TILES, 256, GEMM_SMEM_BYTES>>>(bias, mul, out);
}